// round 1
// baseline (speedup 1.0000x reference)
#include <cuda_runtime.h>
#include <cuda_bf16.h>
#include <cstddef>

// Sorted segment-sum: feat[N_ROWS, 128] fp32 -> out[4096, 128] fp32.
// Each warp owns a contiguous chain of rows; 32 lanes x float4 = one 128-float
// row per iteration. Register accumulation while segment id is constant;
// atomicAdd flush only at segment boundaries (rare: avg segment ~244 rows).

#define WARPS_PER_BLOCK 8
#define THREADS (WARPS_PER_BLOCK * 32)
#define GRID_BLOCKS 1184   // 148 SMs * 8 resident blocks -> single wave
#define D_FEAT 128

__global__ void zero_out_kernel(float4* __restrict__ out, int n4) {
    int i = blockIdx.x * blockDim.x + threadIdx.x;
    if (i < n4) out[i] = make_float4(0.f, 0.f, 0.f, 0.f);
}

__global__ __launch_bounds__(THREADS, 8)
void segsum_kernel(const float4* __restrict__ feat4,
                   const int* __restrict__ seg,
                   float* __restrict__ out,
                   int n_rows) {
    const int warp = threadIdx.x >> 5;
    const int lane = threadIdx.x & 31;

    const long n_chains = (long)gridDim.x * WARPS_PER_BLOCK;
    const long chain = (long)blockIdx.x * WARPS_PER_BLOCK + warp;
    const long rpc = (n_rows + n_chains - 1) / n_chains;
    long r0 = chain * rpc;
    long r1 = r0 + rpc;
    if (r1 > n_rows) r1 = n_rows;
    if (r0 >= r1) return;

    float4 acc = make_float4(0.f, 0.f, 0.f, 0.f);
    int cur = seg[r0];

    for (long r = r0; r < r1; r += 4) {
        const int cnt = (int)((r1 - r) < 4 ? (r1 - r) : 4);
        float4 v[4];
        int s[4];
        // Front-batch loads for MLP before the data-dependent accumulate.
        #pragma unroll
        for (int i = 0; i < 4; i++) {
            if (i < cnt) {
                s[i] = seg[r + i];
                v[i] = feat4[(size_t)(r + i) * (D_FEAT / 4) + lane];
            }
        }
        #pragma unroll
        for (int i = 0; i < 4; i++) {
            if (i < cnt) {
                if (s[i] != cur) {
                    float* dst = out + (size_t)cur * D_FEAT + lane * 4;
                    atomicAdd(dst + 0, acc.x);
                    atomicAdd(dst + 1, acc.y);
                    atomicAdd(dst + 2, acc.z);
                    atomicAdd(dst + 3, acc.w);
                    acc = make_float4(0.f, 0.f, 0.f, 0.f);
                    cur = s[i];
                }
                acc.x += v[i].x;
                acc.y += v[i].y;
                acc.z += v[i].z;
                acc.w += v[i].w;
            }
        }
    }

    float* dst = out + (size_t)cur * D_FEAT + lane * 4;
    atomicAdd(dst + 0, acc.x);
    atomicAdd(dst + 1, acc.y);
    atomicAdd(dst + 2, acc.z);
    atomicAdd(dst + 3, acc.w);
}

extern "C" void kernel_launch(void* const* d_in, const int* in_sizes, int n_in,
                              void* d_out, int out_size) {
    const float* feat = (const float*)d_in[0];
    const int* seg = (const int*)d_in[1];
    float* out = (float*)d_out;

    const int n_rows = in_sizes[0] / D_FEAT;  // 1,000,000
    const int n4 = out_size / 4;              // 4096*128/4 = 131072

    zero_out_kernel<<<(n4 + 255) / 256, 256>>>((float4*)out, n4);
    segsum_kernel<<<GRID_BLOCKS, THREADS>>>((const float4*)feat, seg, out, n_rows);
}

// round 2
// speedup vs baseline: 1.4253x; 1.4253x over previous
#include <cuda_runtime.h>
#include <cuda_bf16.h>
#include <cstddef>

// Sorted segment-sum: feat[1e6, 128] fp32 -> out[4096, 128] fp32.
// One warp per contiguous chain of rows (aligned to 8). Hot loop: 8 rows per
// iteration, all loads unconditional and front-batched (2x int4 seg + 8x
// float4 feat => MLP ~10 per warp). Sortedness trick: if seg[last of batch]
// == cur then the whole batch belongs to the current segment (ids are
// non-decreasing), so the hot path is a single compare + tree-add.
// Segment boundaries (~4096 total) + chain ends (~9472) take the cold path
// with atomicAdd flushes - negligible traffic.

#define WARPS_PER_BLOCK 8
#define THREADS (WARPS_PER_BLOCK * 32)
#define GRID_BLOCKS 1184   // 148 SMs * 8 blocks
#define D_FEAT 128

__global__ void zero_out_kernel(float4* __restrict__ out, int n4) {
    int i = blockIdx.x * blockDim.x + threadIdx.x;
    if (i < n4) out[i] = make_float4(0.f, 0.f, 0.f, 0.f);
}

__device__ __forceinline__ float4 f4add(float4 a, float4 b) {
    return make_float4(a.x + b.x, a.y + b.y, a.z + b.z, a.w + b.w);
}

__global__ __launch_bounds__(THREADS, 4)
void segsum_kernel(const float4* __restrict__ feat4,
                   const int* __restrict__ seg,
                   float* __restrict__ out,
                   int n_rows) {
    const int warp = threadIdx.x >> 5;
    const int lane = threadIdx.x & 31;

    const long n_chains = (long)gridDim.x * WARPS_PER_BLOCK;
    long rpc = (n_rows + n_chains - 1) / n_chains;
    rpc = (rpc + 7) & ~7L;                       // 8-row aligned chains
    const long chain = (long)blockIdx.x * WARPS_PER_BLOCK + warp;
    long r0 = chain * rpc;
    if (r0 >= n_rows) return;
    long r1 = r0 + rpc;
    if (r1 > n_rows) r1 = n_rows;

    float4 acc = make_float4(0.f, 0.f, 0.f, 0.f);
    int cur = seg[r0];

    long r = r0;
    // ---------- hot loop: branch-free loads, 8 rows / iter ----------
    for (; r + 8 <= r1; r += 8) {
        const int4 sA = *reinterpret_cast<const int4*>(seg + r);
        const int4 sB = *reinterpret_cast<const int4*>(seg + r + 4);
        const size_t base = (size_t)r * (D_FEAT / 4) + lane;
        const float4 v0 = feat4[base + 0 * 32];
        const float4 v1 = feat4[base + 1 * 32];
        const float4 v2 = feat4[base + 2 * 32];
        const float4 v3 = feat4[base + 3 * 32];
        const float4 v4 = feat4[base + 4 * 32];
        const float4 v5 = feat4[base + 5 * 32];
        const float4 v6 = feat4[base + 6 * 32];
        const float4 v7 = feat4[base + 7 * 32];

        if (sB.w == cur) {
            // sorted ids: last == cur  =>  all 8 == cur
            float4 t0 = f4add(f4add(v0, v1), f4add(v2, v3));
            float4 t1 = f4add(f4add(v4, v5), f4add(v6, v7));
            acc = f4add(acc, f4add(t0, t1));
        } else {
            // cold path: segment boundary inside this batch
            int s[8] = {sA.x, sA.y, sA.z, sA.w, sB.x, sB.y, sB.z, sB.w};
            float4 v[8] = {v0, v1, v2, v3, v4, v5, v6, v7};
            #pragma unroll
            for (int i = 0; i < 8; i++) {
                if (s[i] != cur) {
                    float* dst = out + (size_t)cur * D_FEAT + lane * 4;
                    atomicAdd(dst + 0, acc.x);
                    atomicAdd(dst + 1, acc.y);
                    atomicAdd(dst + 2, acc.z);
                    atomicAdd(dst + 3, acc.w);
                    acc = make_float4(0.f, 0.f, 0.f, 0.f);
                    cur = s[i];
                }
                acc = f4add(acc, v[i]);
            }
        }
    }
    // ---------- scalar tail (only last chain, if n_rows % 8 != 0) ----------
    for (; r < r1; ++r) {
        int s = seg[r];
        float4 v = feat4[(size_t)r * (D_FEAT / 4) + lane];
        if (s != cur) {
            float* dst = out + (size_t)cur * D_FEAT + lane * 4;
            atomicAdd(dst + 0, acc.x);
            atomicAdd(dst + 1, acc.y);
            atomicAdd(dst + 2, acc.z);
            atomicAdd(dst + 3, acc.w);
            acc = make_float4(0.f, 0.f, 0.f, 0.f);
            cur = s;
        }
        acc = f4add(acc, v);
    }

    float* dst = out + (size_t)cur * D_FEAT + lane * 4;
    atomicAdd(dst + 0, acc.x);
    atomicAdd(dst + 1, acc.y);
    atomicAdd(dst + 2, acc.z);
    atomicAdd(dst + 3, acc.w);
}

extern "C" void kernel_launch(void* const* d_in, const int* in_sizes, int n_in,
                              void* d_out, int out_size) {
    const float* feat = (const float*)d_in[0];
    const int* seg = (const int*)d_in[1];
    float* out = (float*)d_out;

    const int n_rows = in_sizes[0] / D_FEAT;  // 1,000,000
    const int n4 = out_size / 4;              // 131072

    zero_out_kernel<<<(n4 + 255) / 256, 256>>>((float4*)out, n4);
    segsum_kernel<<<GRID_BLOCKS, THREADS>>>((const float4*)feat, seg, out, n_rows);
}

// round 3
// speedup vs baseline: 1.5372x; 1.0785x over previous
#include <cuda_runtime.h>
#include <cuda_bf16.h>
#include <cstddef>

// Sorted segment-sum: feat[1e6, 128] fp32 -> out[4096, 128] fp32.
// One warp per contiguous chain of 8-row tiles, tiles distributed EXACTLY
// evenly across all chains (no idle chains). Grid sized for ~4 waves so
// work-stealing smooths the cross-CTA L1tex-queue spread at the tail.
// Hot loop: 8 rows/iter, branch-free front-batched loads (2x int4 seg +
// 8x float4 feat, streaming hint). Sortedness: last id == cur => whole
// batch == cur. Flushes (chain ends + segment boundaries, ~23K total) go
// through atomicAdd - negligible traffic.

#define WARPS_PER_BLOCK 8
#define THREADS (WARPS_PER_BLOCK * 32)
#define GRID_BLOCKS 2368   // 148 SMs * 16 -> 4 waves at 4 resident blocks/SM
#define D_FEAT 128

__global__ void zero_out_kernel(float4* __restrict__ out, int n4) {
    int i = blockIdx.x * blockDim.x + threadIdx.x;
    if (i < n4) out[i] = make_float4(0.f, 0.f, 0.f, 0.f);
}

__device__ __forceinline__ float4 f4add(float4 a, float4 b) {
    return make_float4(a.x + b.x, a.y + b.y, a.z + b.z, a.w + b.w);
}

__global__ __launch_bounds__(THREADS, 4)
void segsum_kernel(const float4* __restrict__ feat4,
                   const int* __restrict__ seg,
                   float* __restrict__ out,
                   int n_rows) {
    const int warp = threadIdx.x >> 5;
    const int lane = threadIdx.x & 31;

    const long n_chains = (long)GRID_BLOCKS * WARPS_PER_BLOCK;
    const long n_tiles = n_rows >> 3;            // full 8-row tiles
    const long chain = (long)blockIdx.x * WARPS_PER_BLOCK + warp;

    // Balanced split: chain c owns tiles [c*n_tiles/n_chains, (c+1)*n_tiles/n_chains)
    long t0 = (chain * n_tiles) / n_chains;
    long t1 = ((chain + 1) * n_tiles) / n_chains;
    long r0 = t0 << 3;
    long r1 = t1 << 3;
    // Last chain also takes the (n_rows % 8) remainder rows.
    if (chain == n_chains - 1) r1 = n_rows;
    if (r0 >= r1) return;

    float4 acc = make_float4(0.f, 0.f, 0.f, 0.f);
    int cur = seg[r0];

    long r = r0;
    // ---------- hot loop: branch-free loads, 8 rows / iter ----------
    for (; r + 8 <= r1; r += 8) {
        const int4 sA = *reinterpret_cast<const int4*>(seg + r);
        const int4 sB = *reinterpret_cast<const int4*>(seg + r + 4);
        const float4* base = feat4 + (size_t)r * (D_FEAT / 4) + lane;
        const float4 v0 = __ldcs(base + 0 * 32);
        const float4 v1 = __ldcs(base + 1 * 32);
        const float4 v2 = __ldcs(base + 2 * 32);
        const float4 v3 = __ldcs(base + 3 * 32);
        const float4 v4 = __ldcs(base + 4 * 32);
        const float4 v5 = __ldcs(base + 5 * 32);
        const float4 v6 = __ldcs(base + 6 * 32);
        const float4 v7 = __ldcs(base + 7 * 32);

        if (sB.w == cur) {
            // sorted ids: last == cur  =>  all 8 == cur
            float4 t0s = f4add(f4add(v0, v1), f4add(v2, v3));
            float4 t1s = f4add(f4add(v4, v5), f4add(v6, v7));
            acc = f4add(acc, f4add(t0s, t1s));
        } else {
            // cold path: segment boundary inside this batch
            int s[8] = {sA.x, sA.y, sA.z, sA.w, sB.x, sB.y, sB.z, sB.w};
            float4 v[8] = {v0, v1, v2, v3, v4, v5, v6, v7};
            #pragma unroll
            for (int i = 0; i < 8; i++) {
                if (s[i] != cur) {
                    float* dst = out + (size_t)cur * D_FEAT + lane * 4;
                    atomicAdd(dst + 0, acc.x);
                    atomicAdd(dst + 1, acc.y);
                    atomicAdd(dst + 2, acc.z);
                    atomicAdd(dst + 3, acc.w);
                    acc = make_float4(0.f, 0.f, 0.f, 0.f);
                    cur = s[i];
                }
                acc = f4add(acc, v[i]);
            }
        }
    }
    // ---------- scalar tail (only last chain, if n_rows % 8 != 0) ----------
    for (; r < r1; ++r) {
        int s = seg[r];
        float4 v = __ldcs(feat4 + (size_t)r * (D_FEAT / 4) + lane);
        if (s != cur) {
            float* dst = out + (size_t)cur * D_FEAT + lane * 4;
            atomicAdd(dst + 0, acc.x);
            atomicAdd(dst + 1, acc.y);
            atomicAdd(dst + 2, acc.z);
            atomicAdd(dst + 3, acc.w);
            acc = make_float4(0.f, 0.f, 0.f, 0.f);
            cur = s;
        }
        acc = f4add(acc, v);
    }

    float* dst = out + (size_t)cur * D_FEAT + lane * 4;
    atomicAdd(dst + 0, acc.x);
    atomicAdd(dst + 1, acc.y);
    atomicAdd(dst + 2, acc.z);
    atomicAdd(dst + 3, acc.w);
}

extern "C" void kernel_launch(void* const* d_in, const int* in_sizes, int n_in,
                              void* d_out, int out_size) {
    const float* feat = (const float*)d_in[0];
    const int* seg = (const int*)d_in[1];
    float* out = (float*)d_out;

    const int n_rows = in_sizes[0] / D_FEAT;  // 1,000,000
    const int n4 = out_size / 4;              // 131072

    zero_out_kernel<<<(n4 + 255) / 256, 256>>>((float4*)out, n4);
    segsum_kernel<<<GRID_BLOCKS, THREADS>>>((const float4*)feat, seg, out, n_rows);
}